// round 13
// baseline (speedup 1.0000x reference)
#include <cuda_runtime.h>
#include <cuda_bf16.h>
#include <cstdint>

#define NS 512       // sequence length N
#define DD 64        // feature dim d
#define NB 64        // batch B
#define GTJ 64       // column tiles (8 wide each)
#define NDIAG 192    // 128 + 64 - 1 = 191, padded even
#define C2_NEG (-0x40000000)
#define PADF 4096    // guard pad (floats) around g_E
#define SLOT_OFF 256
#define SLOTS 640
#define RING 6       // SMEM ring depth (16KB per slot)
#define L2E 1.4426950408889634f

// Guarded 64MB scratch: E[b,i,j] = exp(-||x_i - y_j||)
__device__ __align__(128) float g_Ebuf[(size_t)PADF + (size_t)NB * NS * NS + PADF];
// bf16-packed operands (u32 = 2 bf16, k-contiguous) + fp32 row norms
__device__ uint32_t g_Xbf[(size_t)NB * NS * (DD / 2)];
__device__ uint32_t g_Ybf[(size_t)NB * NS * (DD / 2)];
__device__ float g_xn[NB * NS];
__device__ float g_yn[NB * NS];

__device__ __forceinline__ uint32_t smem_u32(const void* p) {
    uint32_t a;
    asm("{ .reg .u64 t; cvta.to.shared.u64 t, %1; cvt.u32.u64 %0, t; }"
        : "=r"(a) : "l"(p));
    return a;
}

// ===========================================================================
// Stage 0: fp32 -> bf16 pack + row norms. One warp per row (X and Y).
// ===========================================================================
__global__ void __launch_bounds__(256)
convert_kernel(const float* __restrict__ X, const float* __restrict__ Y) {
    const int gw = blockIdx.x * 8 + (threadIdx.x >> 5);
    const int lane = threadIdx.x & 31;
    const bool isY = gw >= NB * NS;
    const int row = isY ? gw - NB * NS : gw;
    const float* src = (isY ? Y : X) + (size_t)row * DD;

    float2 v = reinterpret_cast<const float2*>(src)[lane];
    float s = v.x * v.x + v.y * v.y;
#pragma unroll
    for (int off = 16; off > 0; off >>= 1)
        s += __shfl_xor_sync(0xffffffffu, s, off);

    __nv_bfloat162 h = __floats2bfloat162_rn(v.x, v.y);
    uint32_t pk = *reinterpret_cast<uint32_t*>(&h);
    (isY ? g_Ybf : g_Xbf)[(size_t)row * 32 + lane] = pk;
    if (lane == 0) (isY ? g_yn : g_xn)[row] = s;
}

// ===========================================================================
// Stage 1: bf16 HMMA cdist (unchanged from R12 — passing at ~20us).
// ===========================================================================
__global__ void __launch_bounds__(256)
cdist_mma(int dummy) {
    const int b  = blockIdx.z;
    const int i0 = blockIdx.y * 128;
    const int j0 = blockIdx.x * 128;
    const int tid = threadIdx.x;
    const int w = tid >> 5, lane = tid & 31;
    const int mw = w & 3, nw = w >> 2;
    const int g = lane >> 2, t = lane & 3;

    const uint32_t* Xu = g_Xbf + ((size_t)b * NS + i0) * 32;
    const uint32_t* Yu = g_Ybf + ((size_t)b * NS + j0) * 32;

    float acc[2][8][4];
#pragma unroll
    for (int mt = 0; mt < 2; ++mt)
#pragma unroll
        for (int nt = 0; nt < 8; ++nt)
#pragma unroll
            for (int q = 0; q < 4; ++q) acc[mt][nt][q] = 0.0f;

    const int rA = mw * 32 + g;
    const int rB = nw * 64 + g;

#pragma unroll
    for (int ks = 0; ks < 4; ++ks) {
        const int kb = ks * 8;
        uint32_t a[2][4];
#pragma unroll
        for (int mt = 0; mt < 2; ++mt) {
            const uint32_t* p = Xu + (size_t)(rA + mt * 16) * 32 + kb + t;
            a[mt][0] = p[0];
            a[mt][1] = p[8 * 32];
            a[mt][2] = p[4];
            a[mt][3] = p[8 * 32 + 4];
        }
#pragma unroll
        for (int nt = 0; nt < 8; ++nt) {
            const uint32_t* q = Yu + (size_t)(rB + nt * 8) * 32 + kb + t;
            uint32_t b0 = q[0], b1 = q[4];
#pragma unroll
            for (int mt = 0; mt < 2; ++mt) {
                asm volatile(
                    "mma.sync.aligned.m16n8k16.row.col.f32.bf16.bf16.f32 "
                    "{%0,%1,%2,%3}, {%4,%5,%6,%7}, {%8,%9}, {%0,%1,%2,%3};"
                    : "+f"(acc[mt][nt][0]), "+f"(acc[mt][nt][1]),
                      "+f"(acc[mt][nt][2]), "+f"(acc[mt][nt][3])
                    : "r"(a[mt][0]), "r"(a[mt][1]),
                      "r"(a[mt][2]), "r"(a[mt][3]),
                      "r"(b0), "r"(b1));
            }
        }
    }

    const float* xnp = g_xn + b * NS + i0;
    const float* ynp = g_yn + b * NS + j0;
#pragma unroll
    for (int mt = 0; mt < 2; ++mt) {
        const int r0 = mw * 32 + mt * 16 + g;
        const int r1 = r0 + 8;
        const float xn0 = xnp[r0], xn1 = xnp[r1];
        float* e0 = g_Ebuf + PADF + ((size_t)b * NS + i0 + r0) * NS + j0;
        float* e1 = g_Ebuf + PADF + ((size_t)b * NS + i0 + r1) * NS + j0;
#pragma unroll
        for (int nt = 0; nt < 8; ++nt) {
            const int c0 = nw * 64 + nt * 8 + 2 * t;
            const float2 yn2 = *reinterpret_cast<const float2*>(ynp + c0);
            float d2; float2 o;
            d2 = xn0 + yn2.x - 2.0f * acc[mt][nt][0];
            o.x = exp2f(-L2E * sqrtf(fmaxf(d2, 0.0f)));
            d2 = xn0 + yn2.y - 2.0f * acc[mt][nt][1];
            o.y = exp2f(-L2E * sqrtf(fmaxf(d2, 0.0f)));
            *reinterpret_cast<float2*>(e0 + c0) = o;
            d2 = xn1 + yn2.x - 2.0f * acc[mt][nt][2];
            o.x = exp2f(-L2E * sqrtf(fmaxf(d2, 0.0f)));
            d2 = xn1 + yn2.y - 2.0f * acc[mt][nt][3];
            o.y = exp2f(-L2E * sqrtf(fmaxf(d2, 0.0f)));
            *reinterpret_cast<float2*>(e1 + c0) = o;
        }
    }
    (void)dummy;
}

// ===========================================================================
// Stage 2: weight-domain soft-DTW, WARP-SPECIALIZED.
// Warps 0-3 consume (DP math, zero LDG); warps 4-7 stream E into a 6-slot
// SMEM ring via cp.async (3-step lookahead, wait_group 2 = 2-step DRAM cover).
// One lockstep __syncthreads per step; warp-uniform role split.
// ===========================================================================
__device__ __forceinline__ float exp2i_neg(int e) {
    return (e >= -126) ? __int_as_float((e + 127) << 23) : 0.0f;
}

__device__ __forceinline__ void subtile4(
    float4 top, int sTop,
    float& cornE, int& cornC2,
    float (&left)[4], int& leftC2,
    float4 e0, float4 e1, float4 e2, float4 e3,
    float4& outB, int& outC2)
{
    int c2 = max(max(sTop, cornC2), leftC2);
    const float ft = exp2i_neg(sTop   - c2);
    const float fc = exp2i_neg(cornC2 - c2);
    const float fl = exp2i_neg(leftC2 - c2);

    float prev[5];
    prev[0] = cornE * fc;
    prev[1] = top.x * ft; prev[2] = top.y * ft;
    prev[3] = top.z * ft; prev[4] = top.w * ft;
    float lE[4] = {left[0] * fl, left[1] * fl, left[2] * fl, left[3] * fl};
    const float newCorn = prev[4];

    float4 dt[4] = {e0, e1, e2, e3};
    float right[4];
#pragma unroll
    for (int a = 0; a < 4; ++a) {
        const float dd0 = dt[a].x, dd1 = dt[a].y, dd2 = dt[a].z, dd3 = dt[a].w;
        float carry = prev[0];
        prev[0] = lE[a];
        float s;
        s = (carry + prev[1]) + prev[0]; carry = prev[1]; prev[1] = dd0 * s;
        s = (carry + prev[2]) + prev[1]; carry = prev[2]; prev[2] = dd1 * s;
        s = (carry + prev[3]) + prev[2]; carry = prev[3]; prev[3] = dd2 * s;
        s = (carry + prev[4]) + prev[3];                  prev[4] = dd3 * s;
        right[a] = prev[4];
    }

    {
        float mr = fmaxf(fmaxf(prev[1], prev[2]), fmaxf(prev[3], prev[4]));
        int mb = __float_as_int(mr);
        float rsr = __int_as_float(0x7F000000 - (mb & 0x7f800000));
        int emr = ((mb >> 23) & 0xff) - 127;
        outB = make_float4(prev[1] * rsr, prev[2] * rsr,
                           prev[3] * rsr, prev[4] * rsr);
        outC2 = (mr > 0.0f) ? (c2 + emr) : C2_NEG;
    }
    {
        float mc = fmaxf(fmaxf(right[0], right[1]), fmaxf(right[2], right[3]));
        int mb = __float_as_int(mc);
        float rsc = __int_as_float(0x7F000000 - (mb & 0x7f800000));
        int emc = ((mb >> 23) & 0xff) - 127;
        left[0] = right[0] * rsc; left[1] = right[1] * rsc;
        left[2] = right[2] * rsc; left[3] = right[3] * rsc;
        leftC2 = (mc > 0.0f) ? (c2 + emc) : C2_NEG;
    }
    {
        int nb = __float_as_int(newCorn);
        cornE  = newCorn * __int_as_float(0x7F000000 - (nb & 0x7f800000));
        cornC2 = (newCorn > 0.0f) ? (c2 + (((nb >> 23) & 0xff) - 127)) : C2_NEG;
    }
}

#define DSM_BYTES (RING * 16384 + 2 * SLOTS * 16 + 2 * SLOTS * 4)

__device__ __forceinline__ void cp_async16(uint32_t dst, const float* src) {
    asm volatile("cp.async.cg.shared.global [%0], [%1], 16;"
                 :: "r"(dst), "l"(src) : "memory");
}

__global__ void __launch_bounds__(256, 1)
dp_kernel(float* __restrict__ out) {
    const int b = blockIdx.x;
    const float* Eb = g_Ebuf + PADF + (size_t)b * NS * NS;

    extern __shared__ __align__(16) char dsm[];
    float4* ringE = reinterpret_cast<float4*>(dsm);              // RING*1024 f4
    float4 (*rowE4)[SLOTS] =
        reinterpret_cast<float4(*)[SLOTS]>(dsm + RING * 16384);
    int (*rowC2s)[SLOTS] =
        reinterpret_cast<int(*)[SLOTS]>(dsm + RING * 16384 + 2 * SLOTS * 16);

    const int tid = threadIdx.x;
    const uint32_t ring_u32 = smem_u32(ringE);

    if (tid < 128) {
        // Consumers: pre-zero frontier slots (both parities).
        float4 z = make_float4(0.f, 0.f, 0.f, 0.f);
        float4* re = &rowE4[0][0];
        for (int s = tid; s < 2 * SLOTS; s += 128) re[s] = z;
        int* rc = &rowC2s[0][0];
        for (int s = tid; s < 2 * SLOTS; s += 128) rc[s] = C2_NEG;
    } else {
        // Producers: prefill ring slots 0..2 (tiles for steps 0..2).
        const int p = tid - 128;
        const float* pg = Eb + (long)p * 4 * NS - (long)p * 8;
#pragma unroll
        for (int t = 0; t < 3; ++t) {
            uint32_t dbase = ring_u32 + t * 16384 + p * 16;
            const float* g = pg + t * 8;
#pragma unroll
            for (int q = 0; q < 8; ++q)
                cp_async16(dbase + q * 2048, g + (q >> 1) * NS + (q & 1) * 4);
            asm volatile("cp.async.commit_group;" ::: "memory");
        }
        asm volatile("cp.async.wait_group 0;" ::: "memory");
    }
    __syncthreads();

    if (tid < 128) {
        // ---------------- Consumer: DP math only ----------------
        const int ti = tid;
        float left[4] = {0.f, 0.f, 0.f, 0.f};
        int leftC2 = C2_NEG;
        float cornE = 0.f;
        int cornC2 = C2_NEG;
        int rslot = 0;

        for (int s = 0; s < NDIAG; ++s) {
            const int tj = s - ti;
            const int wb = s & 1, rb = wb ^ 1;
            const int ix = 2 * tj + SLOT_OFF;

            float4 t0 = rowE4[rb][ix];
            float4 t1 = rowE4[rb][ix + 1];
            int s0 = rowC2s[rb][ix];
            int s1 = rowC2s[rb][ix + 1];

            if (tj == 0) {
                left[0] = left[1] = left[2] = left[3] = 0.0f;
                leftC2 = C2_NEG;
                cornE  = (ti == 0) ? 1.0f : 0.0f;
                cornC2 = (ti == 0) ? 0 : C2_NEG;
            }

            // E tile from SMEM ring (conflict-free LDS.128).
            const float4* rp = ringE + rslot * 1024 + ti;
            float4 cb[8];
#pragma unroll
            for (int q = 0; q < 8; ++q) cb[q] = rp[q * 128];

            float4 b0, b1; int c0, c1;
            subtile4(t0, s0, cornE, cornC2, left, leftC2,
                     cb[0], cb[2], cb[4], cb[6], b0, c0);
            subtile4(t1, s1, cornE, cornC2, left, leftC2,
                     cb[1], cb[3], cb[5], cb[7], b1, c1);

            rowE4[wb][ix]      = b0;
            rowE4[wb][ix + 1]  = b1;
            rowC2s[wb][ix]     = c0;
            rowC2s[wb][ix + 1] = c1;

            rslot = (rslot == RING - 1) ? 0 : rslot + 1;
            __syncthreads();
        }

        if (ti == 0) {
            const int fx = 2 * (GTJ - 1) + SLOT_OFF + 1;
            float e  = fmaxf(rowE4[0][fx].w, 1.17549435e-38f);
            float c2 = (float)rowC2s[0][fx];
            out[b] = -(log2f(e) + c2) * 0.69314718055994530942f;
        }
    } else {
        // ---------------- Producer: stream E into the ring ----------------
        const int p = tid - 128;
        const float* pm = Eb + (long)p * 4 * NS - (long)p * 8 + 3 * 8;
        int wslot = 3;

        for (int s = 0; s < NDIAG; ++s) {
            uint32_t dbase = ring_u32 + wslot * 16384 + p * 16;
#pragma unroll
            for (int q = 0; q < 8; ++q)
                cp_async16(dbase + q * 2048, pm + (q >> 1) * NS + (q & 1) * 4);
            asm volatile("cp.async.commit_group;" ::: "memory");
            asm volatile("cp.async.wait_group 2;" ::: "memory");
            pm += 8;
            wslot = (wslot == RING - 1) ? 0 : wslot + 1;
            __syncthreads();
        }
    }
}

// ---------------------------------------------------------------------------
extern "C" void kernel_launch(void* const* d_in, const int* in_sizes, int n_in,
                              void* d_out, int out_size) {
    (void)in_sizes; (void)n_in; (void)out_size;
    const float* X = (const float*)d_in[0];
    const float* Y = (const float*)d_in[1];
    float* out = (float*)d_out;

    convert_kernel<<<NB * NS * 2 / 8, 256>>>(X, Y);

    dim3 g1(NS / 128, NS / 128, NB);   // (4, 4, 64)
    cdist_mma<<<g1, 256>>>(0);

    cudaFuncSetAttribute(dp_kernel,
                         cudaFuncAttributeMaxDynamicSharedMemorySize,
                         DSM_BYTES);
    dp_kernel<<<NB, 256, DSM_BYTES>>>(out);
}

// round 14
// speedup vs baseline: 1.2107x; 1.2107x over previous
#include <cuda_runtime.h>
#include <cuda_bf16.h>
#include <cstdint>

#define NS 512       // sequence length N
#define DD 64        // feature dim d
#define NB 64        // batch B
#define GTJ 64       // column tiles (8 wide each)
#define NDIAG 192    // 128 + 64 - 1 = 191, padded even
#define C2_NEG (-0x40000000)
#define PADF 4096    // guard pad (floats) around g_E
#define SLOT_OFF 256
#define SLOTS 640
#define SHIFT 90     // prescale alignment headroom (R7-proven)
#define L2E 1.4426950408889634f

// Guarded 64MB scratch: E[b,i,j] = exp(-||x_i - y_j||)
__device__ __align__(128) float g_Ebuf[(size_t)PADF + (size_t)NB * NS * NS + PADF];
// bf16-packed operands (u32 = 2 bf16, k-contiguous) + fp32 row norms
__device__ uint32_t g_Xbf[(size_t)NB * NS * (DD / 2)];
__device__ uint32_t g_Ybf[(size_t)NB * NS * (DD / 2)];
__device__ float g_xn[NB * NS];
__device__ float g_yn[NB * NS];

// ===========================================================================
// Stage 0: fp32 -> bf16 pack + row norms. One warp per row (X and Y).
// ===========================================================================
__global__ void __launch_bounds__(256)
convert_kernel(const float* __restrict__ X, const float* __restrict__ Y) {
    const int gw = blockIdx.x * 8 + (threadIdx.x >> 5);
    const int lane = threadIdx.x & 31;
    const bool isY = gw >= NB * NS;
    const int row = isY ? gw - NB * NS : gw;
    const float* src = (isY ? Y : X) + (size_t)row * DD;

    float2 v = reinterpret_cast<const float2*>(src)[lane];
    float s = v.x * v.x + v.y * v.y;
#pragma unroll
    for (int off = 16; off > 0; off >>= 1)
        s += __shfl_xor_sync(0xffffffffu, s, off);

    __nv_bfloat162 h = __floats2bfloat162_rn(v.x, v.y);
    uint32_t pk = *reinterpret_cast<uint32_t*>(&h);
    (isY ? g_Ybf : g_Xbf)[(size_t)row * 32 + lane] = pk;
    if (lane == 0) (isY ? g_yn : g_xn)[row] = s;
}

// ===========================================================================
// Stage 1: bf16 HMMA cdist (unchanged from R12 — passing).
// ===========================================================================
__global__ void __launch_bounds__(256)
cdist_mma(int dummy) {
    const int b  = blockIdx.z;
    const int i0 = blockIdx.y * 128;
    const int j0 = blockIdx.x * 128;
    const int tid = threadIdx.x;
    const int w = tid >> 5, lane = tid & 31;
    const int mw = w & 3, nw = w >> 2;
    const int g = lane >> 2, t = lane & 3;

    const uint32_t* Xu = g_Xbf + ((size_t)b * NS + i0) * 32;
    const uint32_t* Yu = g_Ybf + ((size_t)b * NS + j0) * 32;

    float acc[2][8][4];
#pragma unroll
    for (int mt = 0; mt < 2; ++mt)
#pragma unroll
        for (int nt = 0; nt < 8; ++nt)
#pragma unroll
            for (int q = 0; q < 4; ++q) acc[mt][nt][q] = 0.0f;

    const int rA = mw * 32 + g;
    const int rB = nw * 64 + g;

#pragma unroll
    for (int ks = 0; ks < 4; ++ks) {
        const int kb = ks * 8;
        uint32_t a[2][4];
#pragma unroll
        for (int mt = 0; mt < 2; ++mt) {
            const uint32_t* p = Xu + (size_t)(rA + mt * 16) * 32 + kb + t;
            a[mt][0] = p[0];
            a[mt][1] = p[8 * 32];
            a[mt][2] = p[4];
            a[mt][3] = p[8 * 32 + 4];
        }
#pragma unroll
        for (int nt = 0; nt < 8; ++nt) {
            const uint32_t* q = Yu + (size_t)(rB + nt * 8) * 32 + kb + t;
            uint32_t b0 = q[0], b1 = q[4];
#pragma unroll
            for (int mt = 0; mt < 2; ++mt) {
                asm volatile(
                    "mma.sync.aligned.m16n8k16.row.col.f32.bf16.bf16.f32 "
                    "{%0,%1,%2,%3}, {%4,%5,%6,%7}, {%8,%9}, {%0,%1,%2,%3};"
                    : "+f"(acc[mt][nt][0]), "+f"(acc[mt][nt][1]),
                      "+f"(acc[mt][nt][2]), "+f"(acc[mt][nt][3])
                    : "r"(a[mt][0]), "r"(a[mt][1]),
                      "r"(a[mt][2]), "r"(a[mt][3]),
                      "r"(b0), "r"(b1));
            }
        }
    }

    const float* xnp = g_xn + b * NS + i0;
    const float* ynp = g_yn + b * NS + j0;
#pragma unroll
    for (int mt = 0; mt < 2; ++mt) {
        const int r0 = mw * 32 + mt * 16 + g;
        const int r1 = r0 + 8;
        const float xn0 = xnp[r0], xn1 = xnp[r1];
        float* e0 = g_Ebuf + PADF + ((size_t)b * NS + i0 + r0) * NS + j0;
        float* e1 = g_Ebuf + PADF + ((size_t)b * NS + i0 + r1) * NS + j0;
#pragma unroll
        for (int nt = 0; nt < 8; ++nt) {
            const int c0 = nw * 64 + nt * 8 + 2 * t;
            const float2 yn2 = *reinterpret_cast<const float2*>(ynp + c0);
            float d2; float2 o;
            d2 = xn0 + yn2.x - 2.0f * acc[mt][nt][0];
            o.x = exp2f(-L2E * sqrtf(fmaxf(d2, 0.0f)));
            d2 = xn0 + yn2.y - 2.0f * acc[mt][nt][1];
            o.y = exp2f(-L2E * sqrtf(fmaxf(d2, 0.0f)));
            *reinterpret_cast<float2*>(e0 + c0) = o;
            d2 = xn1 + yn2.x - 2.0f * acc[mt][nt][2];
            o.x = exp2f(-L2E * sqrtf(fmaxf(d2, 0.0f)));
            d2 = xn1 + yn2.y - 2.0f * acc[mt][nt][3];
            o.y = exp2f(-L2E * sqrtf(fmaxf(d2, 0.0f)));
            *reinterpret_cast<float2*>(e1 + c0) = o;
        }
    }
    (void)dummy;
}

// ===========================================================================
// Stage 2: weight-domain soft-DTW. ANTI-DIAGONAL tile evaluation: the 4x8
// tile's cells are emitted in intra-tile diagonal order (d = row+col), so
// the in-order issue stream carries up to 4 independent cells per latency
// chain link. Single SHIFT-aligned scale group, one merged renorm (R7
// numerics, proven). Frontier: de-clamped offset slots (R12).
// ===========================================================================
__device__ __forceinline__ float exp2i_s(int e) {
    return (e >= -126) ? __int_as_float((e + 127) << 23) : 0.0f;
}

__device__ __forceinline__ void dp_step(
    int kd, int ti, const float* __restrict__ pf,
    const float4 (&cb)[8], float4 (&nb)[8],
    float4 (*rowE4)[SLOTS], int (*rowC2s)[SLOTS],
    float (&left)[4], int& leftC2, float& cornE, int& cornC2,
    float* __restrict__ outp)
{
    const int tj = kd - ti;
    const int wb = kd & 1, rb = wb ^ 1;
    const int ix = 2 * tj + SLOT_OFF;

    float4 t0 = rowE4[rb][ix];
    float4 t1 = rowE4[rb][ix + 1];
    int sTop = rowC2s[rb][ix];

    if (tj == 0) {   // activation reset (predicated)
        left[0] = left[1] = left[2] = left[3] = 0.0f;
        leftC2 = C2_NEG;
        cornE  = (ti == 0) ? 1.0f : 0.0f;
        cornC2 = (ti == 0) ? 0 : C2_NEG;
    }

    // Prefetch next tile (guard-padded, marching pointer).
#pragma unroll
    for (int a = 0; a < 4; ++a) {
        nb[2 * a]     = *reinterpret_cast<const float4*>(pf + a * NS);
        nb[2 * a + 1] = *reinterpret_cast<const float4*>(pf + a * NS + 4);
    }

    // Scale alignment near 2^SHIFT.
    int c2 = max(max(sTop, cornC2), leftC2);
    const float ft = exp2i_s(sTop   - c2 + SHIFT);
    const float fc = exp2i_s(cornC2 - c2 + SHIFT);
    const float fl = exp2i_s(leftC2 - c2 + SHIFT);

    float T[8];
    T[0] = t0.x * ft; T[1] = t0.y * ft; T[2] = t0.z * ft; T[3] = t0.w * ft;
    T[4] = t1.x * ft; T[5] = t1.y * ft; T[6] = t1.z * ft; T[7] = t1.w * ft;
    float L[4] = {left[0] * fl, left[1] * fl, left[2] * fl, left[3] * fl};
    const float C = cornE * fc;
    const float newCorn = T[7];

    // E accessor by constant index (registers after unroll).
    float Ea[4][8];
#pragma unroll
    for (int a = 0; a < 4; ++a) {
        Ea[a][0] = cb[2 * a].x;     Ea[a][1] = cb[2 * a].y;
        Ea[a][2] = cb[2 * a].z;     Ea[a][3] = cb[2 * a].w;
        Ea[a][4] = cb[2 * a + 1].x; Ea[a][5] = cb[2 * a + 1].y;
        Ea[a][6] = cb[2 * a + 1].z; Ea[a][7] = cb[2 * a + 1].w;
    }

    // Anti-diagonal sweep: cells on d = a+q are independent.
    float W[4][8];
#pragma unroll
    for (int d = 0; d < 11; ++d) {
#pragma unroll
        for (int a = 0; a < 4; ++a) {
            const int q = d - a;
            if (q < 0 || q > 7) continue;
            const float dg = (a == 0) ? ((q == 0) ? C : T[q - 1])
                                      : ((q == 0) ? L[a - 1] : W[a - 1][q - 1]);
            const float up = (a == 0) ? T[q] : W[a - 1][q];
            const float lf = (q == 0) ? L[a] : W[a][q - 1];
            W[a][q] = Ea[a][q] * ((dg + up) + lf);
        }
    }

    // Final DP cell: tile (127, 63) computed at kd = 190.
    if (tj == GTJ - 1 && ti == 127) {
        float v = fmaxf(W[3][7], 1.17549435e-38f);
        *outp = -(log2f(v) + (float)(c2 - SHIFT)) * 0.69314718055994530942f;
    }

    // Merged renorm over 12 outputs (bottom row 8 + right col 4).
    float m = fmaxf(fmaxf(fmaxf(W[3][0], W[3][1]), fmaxf(W[3][2], W[3][3])),
                    fmaxf(fmaxf(W[3][4], W[3][5]), fmaxf(W[3][6], W[3][7])));
    m = fmaxf(m, fmaxf(fmaxf(W[0][7], W[1][7]), fmaxf(W[2][7], W[3][7])));
    int mb = __float_as_int(m);
    float rs = __int_as_float(0x7F000000 - (mb & 0x7f800000));   // 2^-em
    int em = ((mb >> 23) & 0xff) - 127;
    int c2n = (m > 0.0f) ? (c2 - SHIFT + em) : C2_NEG;

    float4 o0 = make_float4(W[3][0] * rs, W[3][1] * rs, W[3][2] * rs, W[3][3] * rs);
    float4 o1 = make_float4(W[3][4] * rs, W[3][5] * rs, W[3][6] * rs, W[3][7] * rs);
    left[0] = W[0][7] * rs; left[1] = W[1][7] * rs;
    left[2] = W[2][7] * rs; left[3] = W[3][7] * rs;
    leftC2 = c2n;

    // Corner: own-exponent renorm (scale must track magnitude).
    {
        int nb2 = __float_as_int(newCorn);
        cornE  = newCorn * __int_as_float(0x7F000000 - (nb2 & 0x7f800000));
        cornC2 = (newCorn > 0.0f) ? (c2 - SHIFT + (((nb2 >> 23) & 0xff) - 127))
                                  : C2_NEG;
    }

    rowE4[wb][ix]     = o0;
    rowE4[wb][ix + 1] = o1;
    rowC2s[wb][ix]    = c2n;
    __syncthreads();
}

__global__ void __launch_bounds__(128, 1)
dp_kernel(float* __restrict__ out) {
    const int b = blockIdx.x;
    const float* Eb = g_Ebuf + PADF + (size_t)b * NS * NS;

    __shared__ __align__(16) float4 rowE4[2][SLOTS];
    __shared__ int rowC2s[2][SLOTS];

    const int ti = threadIdx.x;
    const float* Erow0 = Eb + (size_t)(ti * 4) * NS;

    // Pre-zero ALL slots of both parities (boundary + inactive reads).
    {
        float4 z = make_float4(0.f, 0.f, 0.f, 0.f);
        float4* re = &rowE4[0][0];
        for (int s = ti; s < 2 * SLOTS; s += 128) re[s] = z;
        int* rc = &rowC2s[0][0];
        for (int s = ti; s < 2 * SLOTS; s += 128) rc[s] = C2_NEG;
    }

    float4 bufA[8], bufB[8];
#pragma unroll
    for (int a = 0; a < 4; ++a) {   // preload tile tj=0 (ti=0 consumes at kd=0)
        bufA[2 * a]     = *reinterpret_cast<const float4*>(Erow0 + a * NS);
        bufA[2 * a + 1] = *reinterpret_cast<const float4*>(Erow0 + a * NS + 4);
    }
#pragma unroll
    for (int a = 0; a < 8; ++a) bufB[a] = bufA[a];

    float left[4] = {0.f, 0.f, 0.f, 0.f};
    int leftC2 = C2_NEG;
    float cornE = 0.f;
    int cornC2 = C2_NEG;

    __syncthreads();

    const float* pf = Erow0 + (1 - ti) * 8;
    for (int kd = 0; kd < NDIAG; kd += 2) {
        dp_step(kd,     ti, pf,     bufA, bufB, rowE4, rowC2s,
                left, leftC2, cornE, cornC2, out + b);
        dp_step(kd + 1, ti, pf + 8, bufB, bufA, rowE4, rowC2s,
                left, leftC2, cornE, cornC2, out + b);
        pf += 16;
    }
}

// ---------------------------------------------------------------------------
extern "C" void kernel_launch(void* const* d_in, const int* in_sizes, int n_in,
                              void* d_out, int out_size) {
    (void)in_sizes; (void)n_in; (void)out_size;
    const float* X = (const float*)d_in[0];
    const float* Y = (const float*)d_in[1];
    float* out = (float*)d_out;

    convert_kernel<<<NB * NS * 2 / 8, 256>>>(X, Y);

    dim3 g1(NS / 128, NS / 128, NB);   // (4, 4, 64)
    cdist_mma<<<g1, 256>>>(0);

    dp_kernel<<<NB, 128>>>(out);
}

// round 15
// speedup vs baseline: 1.3868x; 1.1454x over previous
#include <cuda_runtime.h>
#include <cuda_bf16.h>
#include <cstdint>

#define NS 512       // sequence length N
#define DD 64        // feature dim d
#define NB 64        // batch B
#define GTJ 64       // column tiles (8 wide each)
#define NDIAG 192    // 128 + 64 - 1 = 191, padded even
#define C2_NEG (-0x40000000)
#define PADF 4096    // guard pad (floats) around g_E
#define SLOT_OFF 256
#define SLOTS 640
#define L2E 1.4426950408889634f

// Guarded 64MB scratch: E[b,i,j] = exp(-||x_i - y_j||)
__device__ __align__(128) float g_Ebuf[(size_t)PADF + (size_t)NB * NS * NS + PADF];

// ===========================================================================
// Stage 1: fused convert + bf16 HMMA cdist.
// Per CTA (grid (4,4,64), 256 thr): stage 128x64 X and Y tiles fp32->bf16 in
// SMEM (row stride 33 u32 -> conflict-free fragment reads), row norms via
// pairwise shfl; then m16n8k16 MMA + fused E = exp(-dist) epilogue.
// ===========================================================================
__global__ void __launch_bounds__(256)
cdist_mma(const float* __restrict__ X, const float* __restrict__ Y) {
    __shared__ uint32_t sA[128 * 33];
    __shared__ uint32_t sB[128 * 33];
    __shared__ float sxn[128], syn[128];

    const int b  = blockIdx.z;
    const int i0 = blockIdx.y * 128;
    const int j0 = blockIdx.x * 128;
    const int tid = threadIdx.x;

    // ---- Stage tiles: thread pair (2 threads/row), 32 floats each ----
    {
        const int r  = tid >> 1;              // 0..127
        const int hf = (tid & 1) * 32;        // float offset in row
        const float* xr = X + ((size_t)b * NS + i0 + r) * DD + hf;
        const float* yr = Y + ((size_t)b * NS + j0 + r) * DD + hf;
        float sx = 0.0f, sy = 0.0f;
        const int base = r * 33 + (hf >> 1);
#pragma unroll
        for (int c = 0; c < 8; ++c) {
            float4 xv = *reinterpret_cast<const float4*>(xr + c * 4);
            float4 yv = *reinterpret_cast<const float4*>(yr + c * 4);
            sx += xv.x * xv.x + xv.y * xv.y + xv.z * xv.z + xv.w * xv.w;
            sy += yv.x * yv.x + yv.y * yv.y + yv.z * yv.z + yv.w * yv.w;
            __nv_bfloat162 h;
            h = __floats2bfloat162_rn(xv.x, xv.y);
            sA[base + c * 2]     = *reinterpret_cast<uint32_t*>(&h);
            h = __floats2bfloat162_rn(xv.z, xv.w);
            sA[base + c * 2 + 1] = *reinterpret_cast<uint32_t*>(&h);
            h = __floats2bfloat162_rn(yv.x, yv.y);
            sB[base + c * 2]     = *reinterpret_cast<uint32_t*>(&h);
            h = __floats2bfloat162_rn(yv.z, yv.w);
            sB[base + c * 2 + 1] = *reinterpret_cast<uint32_t*>(&h);
        }
        sx += __shfl_xor_sync(0xffffffffu, sx, 1);
        sy += __shfl_xor_sync(0xffffffffu, sy, 1);
        if ((tid & 1) == 0) { sxn[r] = sx; syn[r] = sy; }
    }
    __syncthreads();

    // ---- MMA: warp w -> (w&3)*32 rows x (w>>2)*64 cols of the 128x128 tile
    const int w = tid >> 5, lane = tid & 31;
    const int mw = w & 3, nw = w >> 2;
    const int g = lane >> 2, t = lane & 3;

    float acc[2][8][4];
#pragma unroll
    for (int mt = 0; mt < 2; ++mt)
#pragma unroll
        for (int nt = 0; nt < 8; ++nt)
#pragma unroll
            for (int q = 0; q < 4; ++q) acc[mt][nt][q] = 0.0f;

    const int rA = mw * 32 + g;
    const int rB = nw * 64 + g;

#pragma unroll
    for (int ks = 0; ks < 4; ++ks) {
        const int kb = ks * 8;
        uint32_t a[2][4];
#pragma unroll
        for (int mt = 0; mt < 2; ++mt) {
            const int ar = rA + mt * 16;
            a[mt][0] = sA[ar * 33 + kb + t];
            a[mt][1] = sA[(ar + 8) * 33 + kb + t];
            a[mt][2] = sA[ar * 33 + kb + t + 4];
            a[mt][3] = sA[(ar + 8) * 33 + kb + t + 4];
        }
#pragma unroll
        for (int nt = 0; nt < 8; ++nt) {
            const int br = rB + nt * 8;
            uint32_t b0 = sB[br * 33 + kb + t];
            uint32_t b1 = sB[br * 33 + kb + t + 4];
#pragma unroll
            for (int mt = 0; mt < 2; ++mt) {
                asm volatile(
                    "mma.sync.aligned.m16n8k16.row.col.f32.bf16.bf16.f32 "
                    "{%0,%1,%2,%3}, {%4,%5,%6,%7}, {%8,%9}, {%0,%1,%2,%3};"
                    : "+f"(acc[mt][nt][0]), "+f"(acc[mt][nt][1]),
                      "+f"(acc[mt][nt][2]), "+f"(acc[mt][nt][3])
                    : "r"(a[mt][0]), "r"(a[mt][1]),
                      "r"(a[mt][2]), "r"(a[mt][3]),
                      "r"(b0), "r"(b1));
            }
        }
    }

    // ---- Epilogue: E = exp(-sqrt(max(0, xn + yn - 2C))) ----
#pragma unroll
    for (int mt = 0; mt < 2; ++mt) {
        const int r0 = mw * 32 + mt * 16 + g;
        const int r1 = r0 + 8;
        const float xn0 = sxn[r0], xn1 = sxn[r1];
        float* e0 = g_Ebuf + PADF + ((size_t)b * NS + i0 + r0) * NS + j0;
        float* e1 = g_Ebuf + PADF + ((size_t)b * NS + i0 + r1) * NS + j0;
#pragma unroll
        for (int nt = 0; nt < 8; ++nt) {
            const int c0 = nw * 64 + nt * 8 + 2 * t;
            const float ynx = syn[c0], yny = syn[c0 + 1];
            float d2; float2 o;
            d2 = xn0 + ynx - 2.0f * acc[mt][nt][0];
            o.x = exp2f(-L2E * sqrtf(fmaxf(d2, 0.0f)));
            d2 = xn0 + yny - 2.0f * acc[mt][nt][1];
            o.y = exp2f(-L2E * sqrtf(fmaxf(d2, 0.0f)));
            *reinterpret_cast<float2*>(e0 + c0) = o;
            d2 = xn1 + ynx - 2.0f * acc[mt][nt][2];
            o.x = exp2f(-L2E * sqrtf(fmaxf(d2, 0.0f)));
            d2 = xn1 + yny - 2.0f * acc[mt][nt][3];
            o.y = exp2f(-L2E * sqrtf(fmaxf(d2, 0.0f)));
            *reinterpret_cast<float2*>(e1 + c0) = o;
        }
    }
}

// ===========================================================================
// Stage 2: weight-domain soft-DTW (EXACT R12 dp — best measured).
// ===========================================================================
__device__ __forceinline__ float exp2i_neg(int e) {
    return (e >= -126) ? __int_as_float((e + 127) << 23) : 0.0f;
}

__device__ __forceinline__ void subtile4(
    float4 top, int sTop,
    float& cornE, int& cornC2,
    float (&left)[4], int& leftC2,
    float4 e0, float4 e1, float4 e2, float4 e3,
    float4& outB, int& outC2)
{
    int c2 = max(max(sTop, cornC2), leftC2);
    const float ft = exp2i_neg(sTop   - c2);
    const float fc = exp2i_neg(cornC2 - c2);
    const float fl = exp2i_neg(leftC2 - c2);

    float prev[5];
    prev[0] = cornE * fc;
    prev[1] = top.x * ft; prev[2] = top.y * ft;
    prev[3] = top.z * ft; prev[4] = top.w * ft;
    float lE[4] = {left[0] * fl, left[1] * fl, left[2] * fl, left[3] * fl};
    const float newCorn = prev[4];

    float4 dt[4] = {e0, e1, e2, e3};
    float right[4];
#pragma unroll
    for (int a = 0; a < 4; ++a) {
        const float dd0 = dt[a].x, dd1 = dt[a].y, dd2 = dt[a].z, dd3 = dt[a].w;
        float carry = prev[0];
        prev[0] = lE[a];
        float s;
        s = (carry + prev[1]) + prev[0]; carry = prev[1]; prev[1] = dd0 * s;
        s = (carry + prev[2]) + prev[1]; carry = prev[2]; prev[2] = dd1 * s;
        s = (carry + prev[3]) + prev[2]; carry = prev[3]; prev[3] = dd2 * s;
        s = (carry + prev[4]) + prev[3];                  prev[4] = dd3 * s;
        right[a] = prev[4];
    }

    {
        float mr = fmaxf(fmaxf(prev[1], prev[2]), fmaxf(prev[3], prev[4]));
        int mb = __float_as_int(mr);
        float rsr = __int_as_float(0x7F000000 - (mb & 0x7f800000));
        int emr = ((mb >> 23) & 0xff) - 127;
        outB = make_float4(prev[1] * rsr, prev[2] * rsr,
                           prev[3] * rsr, prev[4] * rsr);
        outC2 = (mr > 0.0f) ? (c2 + emr) : C2_NEG;
    }
    {
        float mc = fmaxf(fmaxf(right[0], right[1]), fmaxf(right[2], right[3]));
        int mb = __float_as_int(mc);
        float rsc = __int_as_float(0x7F000000 - (mb & 0x7f800000));
        int emc = ((mb >> 23) & 0xff) - 127;
        left[0] = right[0] * rsc; left[1] = right[1] * rsc;
        left[2] = right[2] * rsc; left[3] = right[3] * rsc;
        leftC2 = (mc > 0.0f) ? (c2 + emc) : C2_NEG;
    }
    {
        int nb = __float_as_int(newCorn);
        cornE  = newCorn * __int_as_float(0x7F000000 - (nb & 0x7f800000));
        cornC2 = (newCorn > 0.0f) ? (c2 + (((nb >> 23) & 0xff) - 127)) : C2_NEG;
    }
}

__device__ __forceinline__ void dp_step(
    int kd, int ti, const float* __restrict__ pf,
    const float4 (&cb)[8], float4 (&nb)[8],
    float4 (*rowE4)[SLOTS], int (*rowC2s)[SLOTS],
    float (&left)[4], int& leftC2, float& cornE, int& cornC2)
{
    const int tj = kd - ti;
    const int wb = kd & 1, rb = wb ^ 1;
    const int ix = 2 * tj + SLOT_OFF;

    float4 t0 = rowE4[rb][ix];
    float4 t1 = rowE4[rb][ix + 1];
    int s0 = rowC2s[rb][ix];
    int s1 = rowC2s[rb][ix + 1];

    if (tj == 0) {   // activation reset (predicated)
        left[0] = left[1] = left[2] = left[3] = 0.0f;
        leftC2 = C2_NEG;
        cornE  = (ti == 0) ? 1.0f : 0.0f;
        cornC2 = (ti == 0) ? 0 : C2_NEG;
    }

    // Prefetch next tile (guard-padded: no clamps, marching pointer).
#pragma unroll
    for (int a = 0; a < 4; ++a) {
        nb[2 * a]     = *reinterpret_cast<const float4*>(pf + a * NS);
        nb[2 * a + 1] = *reinterpret_cast<const float4*>(pf + a * NS + 4);
    }

    float4 b0, b1; int c0, c1;
    subtile4(t0, s0, cornE, cornC2, left, leftC2, cb[0], cb[2], cb[4], cb[6], b0, c0);
    subtile4(t1, s1, cornE, cornC2, left, leftC2, cb[1], cb[3], cb[5], cb[7], b1, c1);

    rowE4[wb][ix]      = b0;
    rowE4[wb][ix + 1]  = b1;
    rowC2s[wb][ix]     = c0;
    rowC2s[wb][ix + 1] = c1;
    __syncthreads();
}

__global__ void __launch_bounds__(128, 1)
dp_kernel(float* __restrict__ out) {
    const int b = blockIdx.x;
    const float* Eb = g_Ebuf + PADF + (size_t)b * NS * NS;

    __shared__ __align__(16) float4 rowE4[2][SLOTS];
    __shared__ int rowC2s[2][SLOTS];

    const int ti = threadIdx.x;
    const float* Erow0 = Eb + (size_t)(ti * 4) * NS;

    // Pre-zero ALL slots of both parities (boundary + inactive reads).
    {
        float4 z = make_float4(0.f, 0.f, 0.f, 0.f);
        float4* re = &rowE4[0][0];
        for (int s = ti; s < 2 * SLOTS; s += 128) re[s] = z;
        int* rc = &rowC2s[0][0];
        for (int s = ti; s < 2 * SLOTS; s += 128) rc[s] = C2_NEG;
    }

    float4 bufA[8], bufB[8];
#pragma unroll
    for (int a = 0; a < 4; ++a) {   // preload tile tj=0 (ti=0 consumes at kd=0)
        bufA[2 * a]     = *reinterpret_cast<const float4*>(Erow0 + a * NS);
        bufA[2 * a + 1] = *reinterpret_cast<const float4*>(Erow0 + a * NS + 4);
    }
#pragma unroll
    for (int a = 0; a < 8; ++a) bufB[a] = bufA[a];

    float left[4] = {0.f, 0.f, 0.f, 0.f};
    int leftC2 = C2_NEG;
    float cornE = 0.f;
    int cornC2 = C2_NEG;

    __syncthreads();

    const float* pf = Erow0 + (1 - ti) * 8;   // column (kd - ti + 1)*8 at kd=0
    for (int kd = 0; kd < NDIAG; kd += 2) {
        dp_step(kd,     ti, pf,     bufA, bufB, rowE4, rowC2s,
                left, leftC2, cornE, cornC2);
        dp_step(kd + 1, ti, pf + 8, bufB, bufA, rowE4, rowC2s,
                left, leftC2, cornE, cornC2);
        pf += 16;
    }

    // Thread 127 wrote tile (127,63) at kd=190 (parity 0), slot 2*63+OFF+1.
    if (ti == 0) {
        const int fx = 2 * (GTJ - 1) + SLOT_OFF + 1;
        float e  = fmaxf(rowE4[0][fx].w, 1.17549435e-38f);
        float c2 = (float)rowC2s[0][fx];
        out[b] = -(log2f(e) + c2) * 0.69314718055994530942f;
    }
}

// ---------------------------------------------------------------------------
extern "C" void kernel_launch(void* const* d_in, const int* in_sizes, int n_in,
                              void* d_out, int out_size) {
    (void)in_sizes; (void)n_in; (void)out_size;
    const float* X = (const float*)d_in[0];
    const float* Y = (const float*)d_in[1];
    float* out = (float*)d_out;

    dim3 g1(NS / 128, NS / 128, NB);   // (4, 4, 64)
    cdist_mma<<<g1, 256>>>(X, Y);

    dp_kernel<<<NB, 128>>>(out);
}

// round 16
// speedup vs baseline: 1.5166x; 1.0936x over previous
#include <cuda_runtime.h>
#include <cuda_bf16.h>
#include <cstdint>

#define NS 512       // sequence length N
#define DD 64        // feature dim d
#define NB 64        // batch B
#define GTJ 64       // column tiles (8 wide each)
#define NDIAG 192    // 128 + 64 - 1 = 191, padded even
#define C2_NEG (-0x40000000)
#define PADF 4096    // guard pad (floats) around g_E
#define SLOT_OFF 256
#define SLOTS 640
#define SROW 20      // uint2 row stride in staged tiles (bank = 8g+2t, CF)
#define L2E 1.4426950408889634f

// Guarded 64MB scratch: E[b,i,j] = exp(-||x_i - y_j||)
__device__ __align__(128) float g_Ebuf[(size_t)PADF + (size_t)NB * NS * NS + PADF];

// ===========================================================================
// Stage 1: fused convert + bf16 HMMA cdist.
// SMEM tiles store HMMA-fragment word PAIRS: entry [row][ks*4+t] = uint2
// { word[8ks+t], word[8ks+t+4] } -> one LDS.64 per b-fragment, two per
// a-fragment pair (halves the mainloop LDS count vs unpaired layout).
// Epilogue uses rsqrt.approx + ex2.approx (2 MUFU + 3 FMUL per element).
// ===========================================================================
__device__ __forceinline__ float edist(float s, float c) {
    float d2 = fmaxf(s - 2.0f * c, 0.0f);
    float r;
    asm("rsqrt.approx.f32 %0, %1;" : "=f"(r) : "f"(fmaxf(d2, 1e-30f)));
    float e;
    asm("ex2.approx.f32 %0, %1;" : "=f"(e) : "f"(-L2E * (d2 * r)));
    return e;
}

__global__ void __launch_bounds__(256)
cdist_mma(const float* __restrict__ X, const float* __restrict__ Y) {
    __shared__ uint2 sA[128 * SROW];
    __shared__ uint2 sB[128 * SROW];
    __shared__ float sxn[128], syn[128];

    const int b  = blockIdx.z;
    const int i0 = blockIdx.y * 128;
    const int j0 = blockIdx.x * 128;
    const int tid = threadIdx.x;

    // ---- Stage tiles: 2 threads/row, each owns 32 floats = 2 ks-blocks ----
    {
        const int r  = tid >> 1;              // 0..127
        const int hw = tid & 1;               // half selector
        const float* xr = X + ((size_t)b * NS + i0 + r) * DD + hw * 32;
        const float* yr = Y + ((size_t)b * NS + j0 + r) * DD + hw * 32;
        float sx = 0.0f, sy = 0.0f;
        uint32_t wx[16], wy[16];
#pragma unroll
        for (int c = 0; c < 8; ++c) {
            float4 xv = *reinterpret_cast<const float4*>(xr + c * 4);
            float4 yv = *reinterpret_cast<const float4*>(yr + c * 4);
            sx += xv.x * xv.x + xv.y * xv.y + xv.z * xv.z + xv.w * xv.w;
            sy += yv.x * yv.x + yv.y * yv.y + yv.z * yv.z + yv.w * yv.w;
            __nv_bfloat162 h;
            h = __floats2bfloat162_rn(xv.x, xv.y);
            wx[c * 2]     = *reinterpret_cast<uint32_t*>(&h);
            h = __floats2bfloat162_rn(xv.z, xv.w);
            wx[c * 2 + 1] = *reinterpret_cast<uint32_t*>(&h);
            h = __floats2bfloat162_rn(yv.x, yv.y);
            wy[c * 2]     = *reinterpret_cast<uint32_t*>(&h);
            h = __floats2bfloat162_rn(yv.z, yv.w);
            wy[c * 2 + 1] = *reinterpret_cast<uint32_t*>(&h);
        }
        // Pack fragment pairs: local ks-block kk covers words kk*8..kk*8+7.
#pragma unroll
        for (int kk = 0; kk < 2; ++kk)
#pragma unroll
            for (int t = 0; t < 4; ++t) {
                const int kc = (hw * 2 + kk) * 4 + t;   // uint2 column 0..15
                sA[r * SROW + kc] = make_uint2(wx[kk * 8 + t], wx[kk * 8 + t + 4]);
                sB[r * SROW + kc] = make_uint2(wy[kk * 8 + t], wy[kk * 8 + t + 4]);
            }
        sx += __shfl_xor_sync(0xffffffffu, sx, 1);
        sy += __shfl_xor_sync(0xffffffffu, sy, 1);
        if (hw == 0) { sxn[r] = sx; syn[r] = sy; }
    }
    __syncthreads();

    // ---- MMA: warp w -> (w&3)*32 rows x (w>>2)*64 cols ----
    const int w = tid >> 5, lane = tid & 31;
    const int mw = w & 3, nw = w >> 2;
    const int g = lane >> 2, t = lane & 3;

    float acc[2][8][4];
#pragma unroll
    for (int mt = 0; mt < 2; ++mt)
#pragma unroll
        for (int nt = 0; nt < 8; ++nt)
#pragma unroll
            for (int q = 0; q < 4; ++q) acc[mt][nt][q] = 0.0f;

    const int rA = mw * 32 + g;
    const int rB = nw * 64 + g;

#pragma unroll
    for (int ks = 0; ks < 4; ++ks) {
        const int kc = ks * 4 + t;
        uint32_t a[2][4];
#pragma unroll
        for (int mt = 0; mt < 2; ++mt) {
            const int ar = rA + mt * 16;
            uint2 v0 = sA[ar * SROW + kc];
            uint2 v1 = sA[(ar + 8) * SROW + kc];
            a[mt][0] = v0.x; a[mt][1] = v1.x;
            a[mt][2] = v0.y; a[mt][3] = v1.y;
        }
#pragma unroll
        for (int nt = 0; nt < 8; ++nt) {
            uint2 vb = sB[(rB + nt * 8) * SROW + kc];
#pragma unroll
            for (int mt = 0; mt < 2; ++mt) {
                asm volatile(
                    "mma.sync.aligned.m16n8k16.row.col.f32.bf16.bf16.f32 "
                    "{%0,%1,%2,%3}, {%4,%5,%6,%7}, {%8,%9}, {%0,%1,%2,%3};"
                    : "+f"(acc[mt][nt][0]), "+f"(acc[mt][nt][1]),
                      "+f"(acc[mt][nt][2]), "+f"(acc[mt][nt][3])
                    : "r"(a[mt][0]), "r"(a[mt][1]),
                      "r"(a[mt][2]), "r"(a[mt][3]),
                      "r"(vb.x), "r"(vb.y));
            }
        }
    }

    // ---- Epilogue: E = exp(-dist) with approx rsqrt/ex2 ----
#pragma unroll
    for (int mt = 0; mt < 2; ++mt) {
        const int r0 = mw * 32 + mt * 16 + g;
        const int r1 = r0 + 8;
        const float xn0 = sxn[r0], xn1 = sxn[r1];
        float* e0 = g_Ebuf + PADF + ((size_t)b * NS + i0 + r0) * NS + j0;
        float* e1 = g_Ebuf + PADF + ((size_t)b * NS + i0 + r1) * NS + j0;
#pragma unroll
        for (int nt = 0; nt < 8; ++nt) {
            const int c0 = nw * 64 + nt * 8 + 2 * t;
            const float ynx = syn[c0], yny = syn[c0 + 1];
            float2 o;
            o.x = edist(xn0 + ynx, acc[mt][nt][0]);
            o.y = edist(xn0 + yny, acc[mt][nt][1]);
            *reinterpret_cast<float2*>(e0 + c0) = o;
            o.x = edist(xn1 + ynx, acc[mt][nt][2]);
            o.y = edist(xn1 + yny, acc[mt][nt][3]);
            *reinterpret_cast<float2*>(e1 + c0) = o;
        }
    }
}

// ===========================================================================
// Stage 2: weight-domain soft-DTW (EXACT R12/R15 dp — frozen champion).
// ===========================================================================
__device__ __forceinline__ float exp2i_neg(int e) {
    return (e >= -126) ? __int_as_float((e + 127) << 23) : 0.0f;
}

__device__ __forceinline__ void subtile4(
    float4 top, int sTop,
    float& cornE, int& cornC2,
    float (&left)[4], int& leftC2,
    float4 e0, float4 e1, float4 e2, float4 e3,
    float4& outB, int& outC2)
{
    int c2 = max(max(sTop, cornC2), leftC2);
    const float ft = exp2i_neg(sTop   - c2);
    const float fc = exp2i_neg(cornC2 - c2);
    const float fl = exp2i_neg(leftC2 - c2);

    float prev[5];
    prev[0] = cornE * fc;
    prev[1] = top.x * ft; prev[2] = top.y * ft;
    prev[3] = top.z * ft; prev[4] = top.w * ft;
    float lE[4] = {left[0] * fl, left[1] * fl, left[2] * fl, left[3] * fl};
    const float newCorn = prev[4];

    float4 dt[4] = {e0, e1, e2, e3};
    float right[4];
#pragma unroll
    for (int a = 0; a < 4; ++a) {
        const float dd0 = dt[a].x, dd1 = dt[a].y, dd2 = dt[a].z, dd3 = dt[a].w;
        float carry = prev[0];
        prev[0] = lE[a];
        float s;
        s = (carry + prev[1]) + prev[0]; carry = prev[1]; prev[1] = dd0 * s;
        s = (carry + prev[2]) + prev[1]; carry = prev[2]; prev[2] = dd1 * s;
        s = (carry + prev[3]) + prev[2]; carry = prev[3]; prev[3] = dd2 * s;
        s = (carry + prev[4]) + prev[3];                  prev[4] = dd3 * s;
        right[a] = prev[4];
    }

    {
        float mr = fmaxf(fmaxf(prev[1], prev[2]), fmaxf(prev[3], prev[4]));
        int mb = __float_as_int(mr);
        float rsr = __int_as_float(0x7F000000 - (mb & 0x7f800000));
        int emr = ((mb >> 23) & 0xff) - 127;
        outB = make_float4(prev[1] * rsr, prev[2] * rsr,
                           prev[3] * rsr, prev[4] * rsr);
        outC2 = (mr > 0.0f) ? (c2 + emr) : C2_NEG;
    }
    {
        float mc = fmaxf(fmaxf(right[0], right[1]), fmaxf(right[2], right[3]));
        int mb = __float_as_int(mc);
        float rsc = __int_as_float(0x7F000000 - (mb & 0x7f800000));
        int emc = ((mb >> 23) & 0xff) - 127;
        left[0] = right[0] * rsc; left[1] = right[1] * rsc;
        left[2] = right[2] * rsc; left[3] = right[3] * rsc;
        leftC2 = (mc > 0.0f) ? (c2 + emc) : C2_NEG;
    }
    {
        int nb = __float_as_int(newCorn);
        cornE  = newCorn * __int_as_float(0x7F000000 - (nb & 0x7f800000));
        cornC2 = (newCorn > 0.0f) ? (c2 + (((nb >> 23) & 0xff) - 127)) : C2_NEG;
    }
}

__device__ __forceinline__ void dp_step(
    int kd, int ti, const float* __restrict__ pf,
    const float4 (&cb)[8], float4 (&nb)[8],
    float4 (*rowE4)[SLOTS], int (*rowC2s)[SLOTS],
    float (&left)[4], int& leftC2, float& cornE, int& cornC2)
{
    const int tj = kd - ti;
    const int wb = kd & 1, rb = wb ^ 1;
    const int ix = 2 * tj + SLOT_OFF;

    float4 t0 = rowE4[rb][ix];
    float4 t1 = rowE4[rb][ix + 1];
    int s0 = rowC2s[rb][ix];
    int s1 = rowC2s[rb][ix + 1];

    if (tj == 0) {   // activation reset (predicated)
        left[0] = left[1] = left[2] = left[3] = 0.0f;
        leftC2 = C2_NEG;
        cornE  = (ti == 0) ? 1.0f : 0.0f;
        cornC2 = (ti == 0) ? 0 : C2_NEG;
    }

    // Prefetch next tile (guard-padded: no clamps, marching pointer).
#pragma unroll
    for (int a = 0; a < 4; ++a) {
        nb[2 * a]     = *reinterpret_cast<const float4*>(pf + a * NS);
        nb[2 * a + 1] = *reinterpret_cast<const float4*>(pf + a * NS + 4);
    }

    float4 b0, b1; int c0, c1;
    subtile4(t0, s0, cornE, cornC2, left, leftC2, cb[0], cb[2], cb[4], cb[6], b0, c0);
    subtile4(t1, s1, cornE, cornC2, left, leftC2, cb[1], cb[3], cb[5], cb[7], b1, c1);

    rowE4[wb][ix]      = b0;
    rowE4[wb][ix + 1]  = b1;
    rowC2s[wb][ix]     = c0;
    rowC2s[wb][ix + 1] = c1;
    __syncthreads();
}

__global__ void __launch_bounds__(128, 1)
dp_kernel(float* __restrict__ out) {
    const int b = blockIdx.x;
    const float* Eb = g_Ebuf + PADF + (size_t)b * NS * NS;

    __shared__ __align__(16) float4 rowE4[2][SLOTS];
    __shared__ int rowC2s[2][SLOTS];

    const int ti = threadIdx.x;
    const float* Erow0 = Eb + (size_t)(ti * 4) * NS;

    // Pre-zero ALL slots of both parities (boundary + inactive reads).
    {
        float4 z = make_float4(0.f, 0.f, 0.f, 0.f);
        float4* re = &rowE4[0][0];
        for (int s = ti; s < 2 * SLOTS; s += 128) re[s] = z;
        int* rc = &rowC2s[0][0];
        for (int s = ti; s < 2 * SLOTS; s += 128) rc[s] = C2_NEG;
    }

    float4 bufA[8], bufB[8];
#pragma unroll
    for (int a = 0; a < 4; ++a) {   // preload tile tj=0 (ti=0 consumes at kd=0)
        bufA[2 * a]     = *reinterpret_cast<const float4*>(Erow0 + a * NS);
        bufA[2 * a + 1] = *reinterpret_cast<const float4*>(Erow0 + a * NS + 4);
    }
#pragma unroll
    for (int a = 0; a < 8; ++a) bufB[a] = bufA[a];

    float left[4] = {0.f, 0.f, 0.f, 0.f};
    int leftC2 = C2_NEG;
    float cornE = 0.f;
    int cornC2 = C2_NEG;

    __syncthreads();

    const float* pf = Erow0 + (1 - ti) * 8;   // column (kd - ti + 1)*8 at kd=0
    for (int kd = 0; kd < NDIAG; kd += 2) {
        dp_step(kd,     ti, pf,     bufA, bufB, rowE4, rowC2s,
                left, leftC2, cornE, cornC2);
        dp_step(kd + 1, ti, pf + 8, bufB, bufA, rowE4, rowC2s,
                left, leftC2, cornE, cornC2);
        pf += 16;
    }

    // Thread 127 wrote tile (127,63) at kd=190 (parity 0), slot 2*63+OFF+1.
    if (ti == 0) {
        const int fx = 2 * (GTJ - 1) + SLOT_OFF + 1;
        float e  = fmaxf(rowE4[0][fx].w, 1.17549435e-38f);
        float c2 = (float)rowC2s[0][fx];
        out[b] = -(log2f(e) + c2) * 0.69314718055994530942f;
    }
}

// ---------------------------------------------------------------------------
extern "C" void kernel_launch(void* const* d_in, const int* in_sizes, int n_in,
                              void* d_out, int out_size) {
    (void)in_sizes; (void)n_in; (void)out_size;
    const float* X = (const float*)d_in[0];
    const float* Y = (const float*)d_in[1];
    float* out = (float*)d_out;

    dim3 g1(NS / 128, NS / 128, NB);   // (4, 4, 64)
    cdist_mma<<<g1, 256>>>(X, Y);

    dp_kernel<<<NB, 128>>>(out);
}

// round 17
// speedup vs baseline: 1.5739x; 1.0378x over previous
#include <cuda_runtime.h>
#include <cuda_bf16.h>
#include <cstdint>

#define NS 512       // sequence length N
#define DD 64        // feature dim d
#define NB 64        // batch B
#define GTJ 64       // column tiles (8 wide each)
#define NDIAG 192    // 128 + 64 - 1 = 191, padded even
#define C2_NEG (-0x40000000)
#define PADF 4096    // guard pad (floats) around g_E
#define SLOT_OFF 256
#define SLOTS 640
#define SROW 20      // uint2 row stride in staged tiles (bank = 8g+2t, CF)
#define SHIFT 90     // prescale alignment headroom (R7-proven envelope)
#define L2E 1.4426950408889634f

// Guarded 64MB scratch: E[b,i,j] = exp(-||x_i - y_j||)
__device__ __align__(128) float g_Ebuf[(size_t)PADF + (size_t)NB * NS * NS + PADF];

// ===========================================================================
// Stage 1: fused convert + bf16 HMMA cdist (R16 structure, proven at ~29us).
// ===========================================================================
__device__ __forceinline__ float edist(float s, float c) {
    float d2 = fmaxf(s - 2.0f * c, 1e-30f);
    float r;
    asm("rsqrt.approx.f32 %0, %1;" : "=f"(r) : "f"(d2));
    float e;
    asm("ex2.approx.f32 %0, %1;" : "=f"(e) : "f"(-L2E * (d2 * r)));
    return e;
}

__global__ void __launch_bounds__(256)
cdist_mma(const float* __restrict__ X, const float* __restrict__ Y) {
    __shared__ uint2 sA[128 * SROW];
    __shared__ uint2 sB[128 * SROW];
    __shared__ float sxn[128], syn[128];

    const int b  = blockIdx.z;
    const int i0 = blockIdx.y * 128;
    const int j0 = blockIdx.x * 128;
    const int tid = threadIdx.x;

    // ---- Stage tiles: 2 threads/row, each owns 32 floats = 2 ks-blocks ----
    {
        const int r  = tid >> 1;              // 0..127
        const int hw = tid & 1;               // half selector
        const float* xr = X + ((size_t)b * NS + i0 + r) * DD + hw * 32;
        const float* yr = Y + ((size_t)b * NS + j0 + r) * DD + hw * 32;
        float sx = 0.0f, sy = 0.0f;
        uint32_t wx[16], wy[16];
#pragma unroll
        for (int c = 0; c < 8; ++c) {
            float4 xv = *reinterpret_cast<const float4*>(xr + c * 4);
            float4 yv = *reinterpret_cast<const float4*>(yr + c * 4);
            sx += xv.x * xv.x + xv.y * xv.y + xv.z * xv.z + xv.w * xv.w;
            sy += yv.x * yv.x + yv.y * yv.y + yv.z * yv.z + yv.w * yv.w;
            __nv_bfloat162 h;
            h = __floats2bfloat162_rn(xv.x, xv.y);
            wx[c * 2]     = *reinterpret_cast<uint32_t*>(&h);
            h = __floats2bfloat162_rn(xv.z, xv.w);
            wx[c * 2 + 1] = *reinterpret_cast<uint32_t*>(&h);
            h = __floats2bfloat162_rn(yv.x, yv.y);
            wy[c * 2]     = *reinterpret_cast<uint32_t*>(&h);
            h = __floats2bfloat162_rn(yv.z, yv.w);
            wy[c * 2 + 1] = *reinterpret_cast<uint32_t*>(&h);
        }
        // Pack fragment pairs: local ks-block kk covers words kk*8..kk*8+7.
#pragma unroll
        for (int kk = 0; kk < 2; ++kk)
#pragma unroll
            for (int t = 0; t < 4; ++t) {
                const int kc = (hw * 2 + kk) * 4 + t;   // uint2 column 0..15
                sA[r * SROW + kc] = make_uint2(wx[kk * 8 + t], wx[kk * 8 + t + 4]);
                sB[r * SROW + kc] = make_uint2(wy[kk * 8 + t], wy[kk * 8 + t + 4]);
            }
        sx += __shfl_xor_sync(0xffffffffu, sx, 1);
        sy += __shfl_xor_sync(0xffffffffu, sy, 1);
        if (hw == 0) { sxn[r] = sx; syn[r] = sy; }
    }
    __syncthreads();

    // ---- MMA: warp w -> (w&3)*32 rows x (w>>2)*64 cols ----
    const int w = tid >> 5, lane = tid & 31;
    const int mw = w & 3, nw = w >> 2;
    const int g = lane >> 2, t = lane & 3;

    float acc[2][8][4];
#pragma unroll
    for (int mt = 0; mt < 2; ++mt)
#pragma unroll
        for (int nt = 0; nt < 8; ++nt)
#pragma unroll
            for (int q = 0; q < 4; ++q) acc[mt][nt][q] = 0.0f;

    const int rA = mw * 32 + g;
    const int rB = nw * 64 + g;

#pragma unroll
    for (int ks = 0; ks < 4; ++ks) {
        const int kc = ks * 4 + t;
        uint32_t a[2][4];
#pragma unroll
        for (int mt = 0; mt < 2; ++mt) {
            const int ar = rA + mt * 16;
            uint2 v0 = sA[ar * SROW + kc];
            uint2 v1 = sA[(ar + 8) * SROW + kc];
            a[mt][0] = v0.x; a[mt][1] = v1.x;
            a[mt][2] = v0.y; a[mt][3] = v1.y;
        }
#pragma unroll
        for (int nt = 0; nt < 8; ++nt) {
            uint2 vb = sB[(rB + nt * 8) * SROW + kc];
#pragma unroll
            for (int mt = 0; mt < 2; ++mt) {
                asm volatile(
                    "mma.sync.aligned.m16n8k16.row.col.f32.bf16.bf16.f32 "
                    "{%0,%1,%2,%3}, {%4,%5,%6,%7}, {%8,%9}, {%0,%1,%2,%3};"
                    : "+f"(acc[mt][nt][0]), "+f"(acc[mt][nt][1]),
                      "+f"(acc[mt][nt][2]), "+f"(acc[mt][nt][3])
                    : "r"(a[mt][0]), "r"(a[mt][1]),
                      "r"(a[mt][2]), "r"(a[mt][3]),
                      "r"(vb.x), "r"(vb.y));
            }
        }
    }

    // ---- Epilogue: E = exp(-dist) with approx rsqrt/ex2 ----
#pragma unroll
    for (int mt = 0; mt < 2; ++mt) {
        const int r0 = mw * 32 + mt * 16 + g;
        const int r1 = r0 + 8;
        const float xn0 = sxn[r0], xn1 = sxn[r1];
        float* e0 = g_Ebuf + PADF + ((size_t)b * NS + i0 + r0) * NS + j0;
        float* e1 = g_Ebuf + PADF + ((size_t)b * NS + i0 + r1) * NS + j0;
#pragma unroll
        for (int nt = 0; nt < 8; ++nt) {
            const int c0 = nw * 64 + nt * 8 + 2 * t;
            const float ynx = syn[c0], yny = syn[c0 + 1];
            float2 o;
            o.x = edist(xn0 + ynx, acc[mt][nt][0]);
            o.y = edist(xn0 + yny, acc[mt][nt][1]);
            *reinterpret_cast<float2*>(e0 + c0) = o;
            o.x = edist(xn1 + ynx, acc[mt][nt][2]);
            o.y = edist(xn1 + yny, acc[mt][nt][3]);
            *reinterpret_cast<float2*>(e1 + c0) = o;
        }
    }
}

// ===========================================================================
// Stage 2: weight-domain soft-DTW.
// HYBRID: R12's two short 4x4 chains (proven fastest chain structure) +
// R7's single SHIFT-aligned scale group and ONE merged renorm per 4x8 tile
// (proven numeric envelope). Subtile B inherits subtile A's aligned scale:
// zero alignment ops for B, one frontier scale per tile.
// ===========================================================================
__device__ __forceinline__ float exp2i_s(int e) {
    return (e >= -126) ? __int_as_float((e + 127) << 23) : 0.0f;
}

// Core 4x4 dependence chain (identical arithmetic/order to R12's subtile4).
__device__ __forceinline__ void chain4(float (&prev)[5], const float (&lE)[4],
                                       float4 e0, float4 e1, float4 e2, float4 e3,
                                       float (&right)[4]) {
    float4 dt[4] = {e0, e1, e2, e3};
#pragma unroll
    for (int a = 0; a < 4; ++a) {
        const float dd0 = dt[a].x, dd1 = dt[a].y, dd2 = dt[a].z, dd3 = dt[a].w;
        float carry = prev[0];
        prev[0] = lE[a];
        float s;
        s = (carry + prev[1]) + prev[0]; carry = prev[1]; prev[1] = dd0 * s;
        s = (carry + prev[2]) + prev[1]; carry = prev[2]; prev[2] = dd1 * s;
        s = (carry + prev[3]) + prev[2]; carry = prev[3]; prev[3] = dd2 * s;
        s = (carry + prev[4]) + prev[3];                  prev[4] = dd3 * s;
        right[a] = prev[4];
    }
}

__device__ __forceinline__ void dp_step(
    int kd, int ti, const float* __restrict__ pf,
    const float4 (&cb)[8], float4 (&nb)[8],
    float4 (*rowE4)[SLOTS], int (*rowC2s)[SLOTS],
    float (&left)[4], int& leftC2, float& cornE, int& cornC2)
{
    const int tj = kd - ti;
    const int wb = kd & 1, rb = wb ^ 1;
    const int ix = 2 * tj + SLOT_OFF;

    float4 t0 = rowE4[rb][ix];
    float4 t1 = rowE4[rb][ix + 1];
    int sTop = rowC2s[rb][ix];

    if (tj == 0) {   // activation reset (predicated)
        left[0] = left[1] = left[2] = left[3] = 0.0f;
        leftC2 = C2_NEG;
        cornE  = (ti == 0) ? 1.0f : 0.0f;
        cornC2 = (ti == 0) ? 0 : C2_NEG;
    }

    // Prefetch next tile (guard-padded: no clamps, marching pointer).
#pragma unroll
    for (int a = 0; a < 4; ++a) {
        nb[2 * a]     = *reinterpret_cast<const float4*>(pf + a * NS);
        nb[2 * a + 1] = *reinterpret_cast<const float4*>(pf + a * NS + 4);
    }

    // --- Single alignment near 2^SHIFT for the whole 4x8 tile ---
    int c2 = max(max(sTop, cornC2), leftC2);
    const float ft = exp2i_s(sTop   - c2 + SHIFT);
    const float fc = exp2i_s(cornC2 - c2 + SHIFT);
    const float fl = exp2i_s(leftC2 - c2 + SHIFT);

    float prevA[5];
    prevA[0] = cornE * fc;
    prevA[1] = t0.x * ft; prevA[2] = t0.y * ft;
    prevA[3] = t0.z * ft; prevA[4] = t0.w * ft;
    float lA[4] = {left[0] * fl, left[1] * fl, left[2] * fl, left[3] * fl};
    const float cornB   = prevA[4];      // aligned R[i0-1][j0+3]
    float TB0 = t1.x * ft, TB1 = t1.y * ft, TB2 = t1.z * ft, TB3 = t1.w * ft;
    const float newCorn = TB3;           // aligned R[i0-1][j0+7]

    // --- Subtile A (cols 0-3) ---
    float rightA[4];
    chain4(prevA, lA, cb[0], cb[2], cb[4], cb[6], rightA);
    const float bA1 = prevA[1], bA2 = prevA[2], bA3 = prevA[3], bA4 = prevA[4];

    // --- Subtile B (cols 4-7): same aligned scale, zero alignment ops ---
    float prevB[5];
    prevB[0] = cornB;
    prevB[1] = TB0; prevB[2] = TB1; prevB[3] = TB2; prevB[4] = TB3;
    float rightB[4];
    chain4(prevB, rightA, cb[1], cb[3], cb[5], cb[7], rightB);

    // --- ONE merged renorm over 12 outputs ---
    float m = fmaxf(fmaxf(fmaxf(bA1, bA2), fmaxf(bA3, bA4)),
                    fmaxf(fmaxf(prevB[1], prevB[2]), fmaxf(prevB[3], prevB[4])));
    m = fmaxf(m, fmaxf(fmaxf(rightB[0], rightB[1]),
                       fmaxf(rightB[2], rightB[3])));
    int mb = __float_as_int(m);
    float rs = __int_as_float(0x7F000000 - (mb & 0x7f800000));   // 2^-em
    int em = ((mb >> 23) & 0xff) - 127;
    int c2n = (m > 0.0f) ? (c2 - SHIFT + em) : C2_NEG;

    float4 o0 = make_float4(bA1 * rs, bA2 * rs, bA3 * rs, bA4 * rs);
    float4 o1 = make_float4(prevB[1] * rs, prevB[2] * rs,
                            prevB[3] * rs, prevB[4] * rs);
    left[0] = rightB[0] * rs; left[1] = rightB[1] * rs;
    left[2] = rightB[2] * rs; left[3] = rightB[3] * rs;
    leftC2 = c2n;

    // Corner: own-exponent renorm (scale must track magnitude).
    {
        int nb2 = __float_as_int(newCorn);
        cornE  = newCorn * __int_as_float(0x7F000000 - (nb2 & 0x7f800000));
        cornC2 = (newCorn > 0.0f) ? (c2 - SHIFT + (((nb2 >> 23) & 0xff) - 127))
                                  : C2_NEG;
    }

    rowE4[wb][ix]     = o0;
    rowE4[wb][ix + 1] = o1;
    rowC2s[wb][ix]    = c2n;
    __syncthreads();
}

__global__ void __launch_bounds__(128, 1)
dp_kernel(float* __restrict__ out) {
    const int b = blockIdx.x;
    const float* Eb = g_Ebuf + PADF + (size_t)b * NS * NS;

    __shared__ __align__(16) float4 rowE4[2][SLOTS];
    __shared__ int rowC2s[2][SLOTS];

    const int ti = threadIdx.x;
    const float* Erow0 = Eb + (size_t)(ti * 4) * NS;

    // Pre-zero ALL slots of both parities (boundary + inactive reads).
    {
        float4 z = make_float4(0.f, 0.f, 0.f, 0.f);
        float4* re = &rowE4[0][0];
        for (int s = ti; s < 2 * SLOTS; s += 128) re[s] = z;
        int* rc = &rowC2s[0][0];
        for (int s = ti; s < 2 * SLOTS; s += 128) rc[s] = C2_NEG;
    }

    float4 bufA[8], bufB[8];
#pragma unroll
    for (int a = 0; a < 4; ++a) {   // preload tile tj=0 (ti=0 consumes at kd=0)
        bufA[2 * a]     = *reinterpret_cast<const float4*>(Erow0 + a * NS);
        bufA[2 * a + 1] = *reinterpret_cast<const float4*>(Erow0 + a * NS + 4);
    }
#pragma unroll
    for (int a = 0; a < 8; ++a) bufB[a] = bufA[a];

    float left[4] = {0.f, 0.f, 0.f, 0.f};
    int leftC2 = C2_NEG;
    float cornE = 0.f;
    int cornC2 = C2_NEG;

    __syncthreads();

    const float* pf = Erow0 + (1 - ti) * 8;   // column (kd - ti + 1)*8 at kd=0
    for (int kd = 0; kd < NDIAG; kd += 2) {
        dp_step(kd,     ti, pf,     bufA, bufB, rowE4, rowC2s,
                left, leftC2, cornE, cornC2);
        dp_step(kd + 1, ti, pf + 8, bufB, bufA, rowE4, rowC2s,
                left, leftC2, cornE, cornC2);
        pf += 16;
    }

    // Thread 127 wrote tile (127,63) at kd=190 (parity 0); value in slot
    // 2*63+OFF+1 (.w), its scale in slot 2*63+OFF.
    if (ti == 0) {
        const int fx = 2 * (GTJ - 1) + SLOT_OFF;
        float e  = fmaxf(rowE4[0][fx + 1].w, 1.17549435e-38f);
        float c2 = (float)rowC2s[0][fx];
        out[b] = -(log2f(e) + c2) * 0.69314718055994530942f;
    }
}

// ---------------------------------------------------------------------------
extern "C" void kernel_launch(void* const* d_in, const int* in_sizes, int n_in,
                              void* d_out, int out_size) {
    (void)in_sizes; (void)n_in; (void)out_size;
    const float* X = (const float*)d_in[0];
    const float* Y = (const float*)d_in[1];
    float* out = (float*)d_out;

    dim3 g1(NS / 128, NS / 128, NB);   // (4, 4, 64)
    cdist_mma<<<g1, 256>>>(X, Y);

    dp_kernel<<<NB, 128>>>(out);
}